// round 11
// baseline (speedup 1.0000x reference)
#include <cuda_runtime.h>
#include <cuda_fp16.h>
#include <cstdint>

#define BB 64
#define SS 2048
#define DD 512
#define UU 256

// M split: 832 tensor tiles x 128 rows = 106496, 384 FFMA tiles x 64 rows = 24576.
// Interleave 13 tensor : 6 ffma per 19 consecutive blockIdx.y (1216 = 19*64).
#define NY 1216
#define M_FFMA0 106496

// ---------------- device scratch (no allocations allowed) ------------------
__device__ float    g_pq[BB * UU];            // q@W2 + b2 + b1
__device__ uint32_t g_Bfrag[2 * 32 * 1024];   // W1 in fp16 MMA-fragment layout
__device__ float    g_spart[4][BB * SS];      // score partials, plane = nc*2+wn
__device__ float    g_partial[32][BB][DD];    // context partials

// ---------------- helpers ---------------------------------------------------
__device__ __forceinline__ uint32_t smem_u32(const void* p) {
    uint32_t a;
    asm("{ .reg .u64 t; cvta.to.shared.u64 t, %1; cvt.u32.u64 %0, t; }"
        : "=r"(a) : "l"(p));
    return a;
}
__device__ __forceinline__ void cp16(uint32_t dst, const void* src) {
    asm volatile("cp.async.cg.shared.global [%0], [%1], 16;" :: "r"(dst), "l"(src));
}
__device__ __forceinline__ uint32_t pack_h2(float lo, float hi) {
    __half2 h = __floats2half2_rn(lo, hi);   // .x = lo (low 16 bits = lower k)
    return *reinterpret_cast<uint32_t*>(&h);
}
// two tanh in one MUFU op (fp16x2 hardware tanh)
__device__ __forceinline__ float2 tanh2(float a, float b) {
    __half2 h = __floats2half2_rn(a, b);
    uint32_t u = *reinterpret_cast<uint32_t*>(&h);
    asm("tanh.approx.f16x2 %0, %0;" : "+r"(u));
    __half2 r = *reinterpret_cast<__half2*>(&u);
    return __half22float2(r);
}
__device__ __forceinline__ void mma_f16(float* d, const uint32_t* a, const uint32_t* b) {
    asm volatile(
        "mma.sync.aligned.m16n8k16.row.col.f32.f16.f16.f32 "
        "{%0,%1,%2,%3}, {%4,%5,%6,%7}, {%8,%9}, {%0,%1,%2,%3};"
        : "+f"(d[0]), "+f"(d[1]), "+f"(d[2]), "+f"(d[3])
        : "r"(a[0]), "r"(a[1]), "r"(a[2]), "r"(a[3]), "r"(b[0]), "r"(b[1]));
}

// ---------------------------------------------------------------------------
// Kernel 1: pq[b,u] = query@W2 + b2 + b1
// ---------------------------------------------------------------------------
__global__ void pq_kernel(const float* __restrict__ query,
                          const float* __restrict__ W2,
                          const float* __restrict__ b2,
                          const float* __restrict__ b1) {
    int b = blockIdx.x;
    int u = threadIdx.x;
    __shared__ float q[DD];
    for (int d = threadIdx.x; d < DD; d += blockDim.x) q[d] = query[b * DD + d];
    __syncthreads();
    float acc = b2[u] + b1[u];
#pragma unroll 8
    for (int d = 0; d < DD; d++) acc += q[d] * W2[d * UU + u];
    g_pq[b * UU + u] = acc;
}

// ---------------------------------------------------------------------------
// Kernel 1b: pack W1 into fp16 m16n8k16 B-fragment layout.
// Word w -> [nc(2)][kc(32)][ntile(16)][lane(32)][kslot(2)]
// ---------------------------------------------------------------------------
__global__ void prep_B(const float* __restrict__ W1) {
    const int w = blockIdx.x * 256 + threadIdx.x;      // 0 .. 65535
    const int nc = w >> 15;
    const int kc = (w >> 10) & 31;
    const int r = w & 1023;
    const int tile = r >> 6, rr = r & 63;
    const int lane = rr >> 1, kslot = rr & 1;
    const int g = lane >> 2, tg = lane & 3;
    const int col = nc * 128 + tile * 8 + g;
    const int row = kc * 16 + kslot * 8 + 2 * tg;
    g_Bfrag[w] = pack_h2(W1[row * UU + col], W1[(row + 1) * UU + col]);
}

// ---------------------------------------------------------------------------
// Kernel 2: HYBRID score kernel. Per block role (uniform per CTA):
//  tensor role (13/19 of blocks): fp16 mma.sync 128x128 tile, proven path.
//  ffma role   (6/19 of blocks):  fp32 SIMT 64x128 tile (R3 structure),
//      runs on the fma pipe, concurrent with tensor CTAs on the same SM.
// Each warp/CTA writes unique rows of its partial plane(s) -> no races.
// ---------------------------------------------------------------------------
__global__ __launch_bounds__(256, 2) void score_tc(
    const float* __restrict__ values,
    const float* __restrict__ W1,
    const float* __restrict__ Vw) {
    __shared__ uint32_t sA[2][1024];   // tensor: 8 m-tiles x 128 words
    __shared__ uint32_t sB[2][1024];   // tensor: 16 n-tiles x 64 words
    __shared__ float sAf[2][8][64];    // ffma A: [buf][k][m]
    __shared__ float sBf[2][8][128];   // ffma B: [buf][k][n]
    __shared__ float pq_s[128], V_s[128];

    const int t = threadIdx.x;
    const int nc = blockIdx.x;                 // 0,1 = N-half
    const int qy = blockIdx.y / 19, ry = blockIdx.y % 19;
    const int wid = t >> 5, lane = t & 31;

    if (ry < 13) {
        // =================== TENSOR ROLE (unchanged logic) ==================
        const size_t m0 = (size_t)(qy * 13 + ry) * 128;
        const int b = (int)(m0 >> 11);
        if (t < 128) {
            pq_s[t] = g_pq[b * UU + nc * 128 + t];
            V_s[t] = Vw[nc * 128 + t];
        }

        const int ar = t >> 1;
        const int ac8 = (t & 1) * 8;
        const float* gA = values + (m0 + ar) * DD + ac8;
        const int a_tm = ar >> 4;
        const int arr = ar & 15;
        const int g_o = arr & 7, rslot = arr >> 3;
        const uint32_t* gBbase = g_Bfrag + (size_t)nc * 32 * 1024 + t * 4;
        const uint32_t sB0 = smem_u32(sB);

        const int wm = wid >> 1, wn = wid & 1;
        const int g = lane >> 2, tg = lane & 3;

        float acc[2][8][4];
#pragma unroll
        for (int i = 0; i < 2; i++)
#pragma unroll
            for (int j = 0; j < 8; j++)
#pragma unroll
                for (int r = 0; r < 4; r++) acc[i][j][r] = 0.f;

        float ra[8];

#define GLOADA(kc) do {                                                       \
        const float* pa_ = gA + (kc) * 16;                                    \
        *(float4*)&ra[0] = *(const float4*)pa_;                               \
        *(float4*)&ra[4] = *(const float4*)(pa_ + 4);                        \
    } while (0)

#define SSTOREA(buf) do {                                                     \
        _Pragma("unroll")                                                     \
        for (int jp_ = 0; jp_ < 4; jp_++) {                                   \
            const int kw_ = (ac8 >> 1) + jp_;                                 \
            const int tg_ = kw_ & 3, ks_ = kw_ >> 2;                          \
            sA[buf][a_tm * 128 + (g_o * 4 + tg_) * 4 + rslot + 2 * ks_] =     \
                pack_h2(ra[2 * jp_], ra[2 * jp_ + 1]);                        \
        }                                                                     \
    } while (0)

#define CPB(kc, buf) do {                                                     \
        cp16(sB0 + ((buf) * 1024 + t * 4) * 4, gBbase + (size_t)(kc) * 1024); \
        asm volatile("cp.async.commit_group;" ::: "memory");                  \
    } while (0)

        CPB(0, 0);
        GLOADA(0);
        SSTOREA(0);
        asm volatile("cp.async.wait_group 0;" ::: "memory");
        __syncthreads();

        for (int kc = 0; kc < 32; kc++) {
            const int p = kc & 1;
            if (kc < 31) {
                CPB(kc + 1, 1 - p);
                GLOADA(kc + 1);
            }

            uint32_t af[2][4];
            *(uint4*)af[0] = *(const uint4*)&sA[p][(wm * 2 + 0) * 128 + lane * 4];
            *(uint4*)af[1] = *(const uint4*)&sA[p][(wm * 2 + 1) * 128 + lane * 4];
            uint32_t bf[8][2];
#pragma unroll
            for (int j = 0; j < 8; j++)
                *(uint2*)bf[j] = *(const uint2*)&sB[p][(wn * 8 + j) * 64 + lane * 2];
#pragma unroll
            for (int j = 0; j < 8; j++) {
                mma_f16(acc[0][j], af[0], bf[j]);
                mma_f16(acc[1][j], af[1], bf[j]);
            }

            if (kc < 31) {
                SSTOREA(1 - p);
                asm volatile("cp.async.wait_group 0;" ::: "memory");
                __syncthreads();
            }
        }

        float* plane = g_spart[nc * 2 + wn];
#pragma unroll
        for (int i = 0; i < 2; i++) {
            float p0 = 0.f, p1 = 0.f;
#pragma unroll
            for (int j = 0; j < 8; j++) {
                const int c0 = wn * 64 + j * 8 + 2 * tg;
                const float q0 = pq_s[c0], q1 = pq_s[c0 + 1];
                const float v0 = V_s[c0], v1 = V_s[c0 + 1];
                const float2 t01 = tanh2(acc[0 + 0][j][0], 0.f);  // placeholder avoided below
                (void)t01;
                const float2 u01 = tanh2(acc[i][j][0] + q0, acc[i][j][1] + q1);
                const float2 u23 = tanh2(acc[i][j][2] + q0, acc[i][j][3] + q1);
                p0 += u01.x * v0 + u01.y * v1;
                p1 += u23.x * v0 + u23.y * v1;
            }
            p0 += __shfl_xor_sync(0xffffffffu, p0, 1);
            p0 += __shfl_xor_sync(0xffffffffu, p0, 2);
            p1 += __shfl_xor_sync(0xffffffffu, p1, 1);
            p1 += __shfl_xor_sync(0xffffffffu, p1, 2);
            if (tg == 0) {
                const size_t row = m0 + wm * 32 + i * 16 + g;
                plane[row] = p0;
                plane[row + 8] = p1;
            }
        }
    } else {
        // ==================== FFMA ROLE (fp32, fma pipe) ====================
        const size_t m0f = M_FFMA0 + (size_t)(qy * 6 + (ry - 13)) * 64;
        const int b = (int)(m0f >> 11);
        if (t < 128) {
            pq_s[t] = g_pq[b * UU + nc * 128 + t];
            V_s[t] = Vw[nc * 128 + t];
        }

        const int am = t >> 2;            // A row 0..63
        const int akg = (t & 3) * 2;      // k offset 0,2,4,6
        const float* gAf = values + (m0f + am) * DD + akg;
        const int bkf = t >> 5;           // B k-row 0..7
        const int bcf = (t & 31) * 4;     // B n col group
        const float* gBf = W1 + (size_t)bkf * UU + nc * 128 + bcf;

        const int ty = t >> 4, tx = t & 15;

        float acc[4][8];
#pragma unroll
        for (int i = 0; i < 4; i++)
#pragma unroll
            for (int j = 0; j < 8; j++) acc[i][j] = 0.f;

        float2 av = *(const float2*)gAf;
        float4 bv = *(const float4*)gBf;
        sAf[0][akg][am] = av.x;
        sAf[0][akg + 1][am] = av.y;
        *(float4*)&sBf[0][bkf][bcf] = bv;
        __syncthreads();

        for (int kc = 0; kc < 64; kc++) {
            const int p = kc & 1;
            if (kc + 1 < 64) {
                av = *(const float2*)(gAf + (kc + 1) * 8);
                bv = *(const float4*)(W1 + (size_t)((kc + 1) * 8 + bkf) * UU + nc * 128 + bcf);
            }

#pragma unroll
            for (int k = 0; k < 8; k++) {
                float a[4], bb[8];
                *(float4*)a = *(const float4*)&sAf[p][k][ty * 4];
                *(float4*)&bb[0] = *(const float4*)&sBf[p][k][tx * 4];
                *(float4*)&bb[4] = *(const float4*)&sBf[p][k][64 + tx * 4];
#pragma unroll
                for (int i = 0; i < 4; i++)
#pragma unroll
                    for (int j = 0; j < 8; j++) acc[i][j] += a[i] * bb[j];
            }

            if (kc + 1 < 64) {
                const int q = p ^ 1;
                sAf[q][akg][am] = av.x;
                sAf[q][akg + 1][am] = av.y;
                *(float4*)&sBf[q][bkf][bcf] = bv;
                __syncthreads();
            }
        }

        // epilogue: full 128-col partial into plane nc*2, zero into nc*2+1
        float sp[4] = {0.f, 0.f, 0.f, 0.f};
#pragma unroll
        for (int j = 0; j < 8; j++) {
            const int col = (j >> 2) * 64 + tx * 4 + (j & 3);
            const float c = pq_s[col];
            const float v = V_s[col];
#pragma unroll
            for (int i = 0; i < 4; i++) sp[i] += tanhf(acc[i][j] + c) * v;
        }
#pragma unroll
        for (int i = 0; i < 4; i++) {
            float s = sp[i];
            s += __shfl_xor_sync(0xffffffffu, s, 1);
            s += __shfl_xor_sync(0xffffffffu, s, 2);
            s += __shfl_xor_sync(0xffffffffu, s, 4);
            s += __shfl_xor_sync(0xffffffffu, s, 8);
            if (tx == 0) {
                const size_t row = m0f + ty * 4 + i;
                g_spart[nc * 2][row] = s;
                g_spart[nc * 2 + 1][row] = 0.f;
            }
        }
    }
}

// ---------------------------------------------------------------------------
// Kernel 3: softmax over S=2048 per batch; sums 4 partial planes, writes attn.
// ---------------------------------------------------------------------------
__global__ void softmax_kernel(float* __restrict__ attn) {
    const int b = blockIdx.x;
    const int t = threadIdx.x;
    __shared__ float red[256];
    float v[8];
    float mx = -1e30f;
#pragma unroll
    for (int i = 0; i < 8; i++) {
        const int idx = b * SS + i * 256 + t;
        v[i] = (g_spart[0][idx] + g_spart[1][idx]) +
               (g_spart[2][idx] + g_spart[3][idx]);
        mx = fmaxf(mx, v[i]);
    }
    red[t] = mx;
    __syncthreads();
    for (int s = 128; s > 0; s >>= 1) {
        if (t < s) red[t] = fmaxf(red[t], red[t + s]);
        __syncthreads();
    }
    mx = red[0];
    __syncthreads();
    float sum = 0.f;
#pragma unroll
    for (int i = 0; i < 8; i++) {
        v[i] = expf(v[i] - mx);
        sum += v[i];
    }
    red[t] = sum;
    __syncthreads();
    for (int s = 128; s > 0; s >>= 1) {
        if (t < s) red[t] += red[t + s];
        __syncthreads();
    }
    const float inv = 1.f / red[0];
#pragma unroll
    for (int i = 0; i < 8; i++) attn[b * SS + i * 256 + t] = v[i] * inv;
}

// ---------------------------------------------------------------------------
// Kernel 4a: context partials. grid (B, 32), 128 threads, float4 per thread.
// ---------------------------------------------------------------------------
__global__ __launch_bounds__(128) void ctx_partial(
    const float* __restrict__ values, const float* __restrict__ attn) {
    const int b = blockIdx.x;
    const int sc = blockIdx.y;
    const int t = threadIdx.x;
    __shared__ float a[64];
    if (t < 64) a[t] = attn[b * SS + sc * 64 + t];
    __syncthreads();
    const float4* vp = (const float4*)(values + ((size_t)b * SS + (size_t)sc * 64) * DD);
    float4 acc = make_float4(0.f, 0.f, 0.f, 0.f);
#pragma unroll 8
    for (int s = 0; s < 64; s++) {
        const float w = a[s];
        const float4 v = vp[(size_t)s * 128 + t];
        acc.x += w * v.x; acc.y += w * v.y; acc.z += w * v.z; acc.w += w * v.w;
    }
    *(float4*)&g_partial[sc][b][t * 4] = acc;
}

// Kernel 4b: reduce the 32 partials.
__global__ void ctx_reduce(float* __restrict__ ctx) {
    const int idx = blockIdx.x * 256 + threadIdx.x;
    const int b = idx / DD, d = idx % DD;
    float s = 0.f;
#pragma unroll
    for (int c = 0; c < 32; c++) s += g_partial[c][b][d];
    ctx[idx] = s;
}

// ---------------------------------------------------------------------------
extern "C" void kernel_launch(void* const* d_in, const int* in_sizes, int n_in,
                              void* d_out, int out_size) {
    const float* query  = (const float*)d_in[0];
    const float* values = (const float*)d_in[1];
    const float* W1     = (const float*)d_in[2];
    const float* b1     = (const float*)d_in[3];
    const float* W2     = (const float*)d_in[4];
    const float* b2     = (const float*)d_in[5];
    const float* Vw     = (const float*)d_in[6];
    // d_in[7] = bV: softmax is shift-invariant -> cannot affect attn or context.

    float* out  = (float*)d_out;
    float* ctx  = out;            // [B*D]
    float* attn = out + BB * DD;  // [B*S]

    pq_kernel<<<BB, UU>>>(query, W2, b2, b1);
    prep_B<<<256, 256>>>(W1);
    score_tc<<<dim3(2, NY), 256>>>(values, W1, Vw);
    softmax_kernel<<<BB, 256>>>(attn);
    ctx_partial<<<dim3(BB, 32), 128>>>(values, attn);
    ctx_reduce<<<(BB * DD) / 256, 256>>>(ctx);
}